// round 2
// baseline (speedup 1.0000x reference)
#include <cuda_runtime.h>
#include <cstdint>

// Problem constants
#define BB   8
#define CIN  64
#define COUT 128
#define HH   224
#define WW   224
#define PTCH 16
#define GG   14     // 14x14 patch grid
#define NP   196

typedef unsigned long long u64;

// Scratch (device globals — no allocations allowed)
__device__ u64 g_sx[BB * HH * WW];   // packed sign(x), bit c = sign of channel c
__device__ u64 g_m [BB * HH * WW];   // nonzero mask of bsa
__device__ u64 g_s [BB * HH * WW];   // sign bit of bsa (1 = negative)
__device__ u64 g_pw[NP * 9];         // packed sign(patch_filters) per (patch, tap)
__device__ u64 g_ow[COUT * 9];       // packed sign(output_filters) per (o, tap)

// ---------------------------------------------------------------------------
// Kernel 0: pack sign bits of x: [B, C=64, H, W] -> u64 per (b, y, x)
// ---------------------------------------------------------------------------
__global__ void pack_x_kernel(const float* __restrict__ x) {
    int pix = blockIdx.x * blockDim.x + threadIdx.x;
    if (pix >= BB * HH * WW) return;
    int b   = pix / (HH * WW);
    int rem = pix - b * (HH * WW);
    const float* xp = x + (size_t)b * CIN * HH * WW + rem;
    u64 w = 0;
#pragma unroll
    for (int c = 0; c < CIN; c++) {
        unsigned sb = __float_as_uint(xp[(size_t)c * HH * WW]) >> 31;
        w |= (u64)sb << c;
    }
    g_sx[pix] = w;
}

// ---------------------------------------------------------------------------
// Kernel 0b: pack filter sign bits
//   patch_filters: [CIN, NP, 1, 3, 3]  -> g_pw[p*9+t] bits over c
//   output_filters:[COUT, CIN, 3, 3]   -> g_ow[o*9+t] bits over c
// ---------------------------------------------------------------------------
__global__ void pack_filters_kernel(const float* __restrict__ pf,
                                    const float* __restrict__ of) {
    int i = blockIdx.x * blockDim.x + threadIdx.x;
    if (i < NP * 9) {
        int p = i / 9, t = i - p * 9;
        u64 w = 0;
#pragma unroll
        for (int c = 0; c < CIN; c++) {
            unsigned sb = __float_as_uint(pf[((size_t)c * NP + p) * 9 + t]) >> 31;
            w |= (u64)sb << c;
        }
        g_pw[i] = w;
    } else if (i < NP * 9 + COUT * 9) {
        int j = i - NP * 9;
        int o = j / 9, t = j - o * 9;
        u64 w = 0;
#pragma unroll
        for (int c = 0; c < CIN; c++) {
            unsigned sb = __float_as_uint(of[((size_t)o * CIN + c) * 9 + t]) >> 31;
            w |= (u64)sb << c;
        }
        g_ow[j] = w;
    }
}

// ---------------------------------------------------------------------------
// Kernel 1: per-patch depthwise binary 3x3 conv (zero pad inside 16x16 patch),
// then ternary quantize: sa = n_valid - 2*mismatch; emit m (sa!=0), s (sa<0).
// One block per (gx, gy, b) patch; 16x16 threads.
// ---------------------------------------------------------------------------
__global__ void __launch_bounds__(256) stage1_kernel() {
    __shared__ u64 tile[PTCH][PTCH];
    __shared__ u64 pw9[9];

    const int gx = blockIdx.x, gy = blockIdx.y, b = blockIdx.z;
    const int j = threadIdx.x, i = threadIdx.y;   // local (col, row) in patch
    const int tid = i * PTCH + j;
    const int patch = gy * GG + gx;

    const int y = gy * PTCH + i;
    const int x = gx * PTCH + j;
    const int pixbase = b * HH * WW;

    tile[i][j] = g_sx[pixbase + y * WW + x];
    if (tid < 9) pw9[tid] = g_pw[patch * 9 + tid];
    __syncthreads();

    // Bit-sliced mismatch counter (4 bits per channel lane)
    u64 c0 = 0, c1 = 0, c2 = 0, c3 = 0;
#pragma unroll
    for (int di = 0; di < 3; di++) {
#pragma unroll
        for (int dj = 0; dj < 3; dj++) {
            int li = i + di - 1, lj = j + dj - 1;
            if (li >= 0 && li < PTCH && lj >= 0 && lj < PTCH) {
                u64 d = tile[li][lj] ^ pw9[di * 3 + dj];
                u64 carry = d, u;
                u = c0 & carry; c0 ^= carry; carry = u;
                u = c1 & carry; c1 ^= carry; carry = u;
                u = c2 & carry; c2 ^= carry; carry = u;
                c3 ^= carry;
            }
        }
    }

    const int ni = (i == 0 || i == PTCH - 1) ? 2 : 3;
    const int nj = (j == 0 || j == PTCH - 1) ? 2 : 3;
    const int n  = ni * nj;   // valid taps: 4, 6, or 9

    u64 m, s;
    if (n == 9) {
        // sa = 9 - 2*cnt: odd, never zero. negative iff cnt >= 5
        m = ~0ULL;
        s = c3 | (c2 & (c1 | c0));
    } else if (n == 6) {
        // zero iff cnt == 3; negative iff cnt >= 4 (<=> c2)
        m = ~(c0 & c1 & ~c2);
        s = c2;
    } else { // n == 4
        // zero iff cnt == 2; negative iff cnt >= 3
        m = ~(c1 & ~c0 & ~c2);
        s = (c0 & c1) | c2;
    }

    g_m[pixbase + y * WW + x] = m;
    g_s[pixbase + y * WW + x] = s;
}

// ---------------------------------------------------------------------------
// Kernel 2: final binary 3x3 conv, 64 -> 128 channels, image-level zero pad.
// out[b,o,y,x] = sum_t popc(m_t) - 2 * sum_t popc(m_t & (s_t ^ w_{o,t}))
// Block: 32x8 pixel tile; each thread computes all 128 output channels.
// ---------------------------------------------------------------------------
#define TX 32
#define TY 8

__global__ void __launch_bounds__(256) stage2_kernel(float* __restrict__ out) {
    __shared__ u64 smM[TY + 2][TX + 2];
    __shared__ u64 smS[TY + 2][TX + 2];
    __shared__ u64 smW[COUT * 9];

    const int b  = blockIdx.z;
    const int x0 = blockIdx.x * TX;
    const int y0 = blockIdx.y * TY;
    const int tx = threadIdx.x, ty = threadIdx.y;
    const int tid = ty * TX + tx;

    // Load halo tile of (m, s)
    for (int idx = tid; idx < (TY + 2) * (TX + 2); idx += TX * TY) {
        int ly = idx / (TX + 2), lx = idx - ly * (TX + 2);
        int gy = y0 - 1 + ly, gx = x0 - 1 + lx;
        u64 m = 0, s = 0;
        if (gy >= 0 && gy < HH && gx >= 0 && gx < WW) {
            int p = b * HH * WW + gy * WW + gx;
            m = g_m[p];
            s = g_s[p];
        }
        smM[ly][lx] = m;
        smS[ly][lx] = s;
    }
    // Load packed weights
    for (int idx = tid; idx < COUT * 9; idx += TX * TY)
        smW[idx] = g_ow[idx];
    __syncthreads();

    // Keep this pixel's 9 neighbor words in registers
    u64 mm[9], ss[9];
#pragma unroll
    for (int di = 0; di < 3; di++)
#pragma unroll
        for (int dj = 0; dj < 3; dj++) {
            mm[di * 3 + dj] = smM[ty + di][tx + dj];
            ss[di * 3 + dj] = smS[ty + di][tx + dj];
        }

    int base = 0;
#pragma unroll
    for (int t = 0; t < 9; t++) base += __popcll(mm[t]);

    float* op = out + ((size_t)b * COUT) * HH * WW + (size_t)(y0 + ty) * WW + (x0 + tx);

#pragma unroll 4
    for (int o = 0; o < COUT; o++) {
        int acc = 0;
#pragma unroll
        for (int t = 0; t < 9; t++)
            acc += __popcll(mm[t] & (ss[t] ^ smW[o * 9 + t]));
        op[(size_t)o * HH * WW] = (float)(base - 2 * acc);
    }
}

// ---------------------------------------------------------------------------
// Launch
// Inputs (metadata order): x [8,64,224,224] f32, a [1] f32 (unused),
//   patch_filters [64,196,1,3,3] f32, output_filters [128,64,3,3] f32.
// Output: [8,128,224,224] f32.
// ---------------------------------------------------------------------------
extern "C" void kernel_launch(void* const* d_in, const int* in_sizes, int n_in,
                              void* d_out, int out_size) {
    const float* x  = (const float*)d_in[0];
    const float* pf = (const float*)d_in[2];
    const float* of = (const float*)d_in[3];
    float* out = (float*)d_out;

    const int npix = BB * HH * WW;
    pack_x_kernel<<<(npix + 255) / 256, 256>>>(x);

    const int nw = NP * 9 + COUT * 9;
    pack_filters_kernel<<<(nw + 255) / 256, 256>>>(pf, of);

    stage1_kernel<<<dim3(GG, GG, BB), dim3(PTCH, PTCH)>>>();

    stage2_kernel<<<dim3(WW / TX, HH / TY, BB), dim3(TX, TY)>>>(out);
}